// round 8
// baseline (speedup 1.0000x reference)
#include <cuda_runtime.h>
#include <cuda_fp16.h>
#include <math.h>
#include <stdint.h>

// Problem constants
#define BT   4096
#define DM   1024
#define DFFN 4096
#define SEQ  2048
#define NH   16
#define DH   64

// ---------------- scratch (device globals) ----------------
__device__ __half g_h  [BT * DM];
__device__ __half g_qkv[BT * 3 * DM];
__device__ __half g_at [BT * DM];
__device__ float  g_x1 [BT * DM];
__device__ __half g_h2 [BT * DM];
__device__ __half g_ff [BT * DFFN];
__device__ __half g_wqkv[3 * DM * DM];   // [3072,1024] (transposed, fp16)
__device__ __half g_wo [DM * DM];
__device__ __half g_w1 [DFFN * DM];      // [4096,1024]
__device__ __half g_w2 [DM * DFFN];      // [1024,4096]

// ---------------- PTX helpers (base sm_80+ PTX only) ----------------
__device__ __forceinline__ uint32_t smem_u32(const void* p) {
    return (uint32_t)__cvta_generic_to_shared(p);
}
__device__ __forceinline__ void cp16(uint32_t dst, const void* src) {
    asm volatile("cp.async.cg.shared.global [%0], [%1], 16;" :: "r"(dst), "l"(src));
}
__device__ __forceinline__ void ldsm4(uint32_t* r, uint32_t addr) {
    asm volatile("ldmatrix.sync.aligned.m8n8.x4.shared.b16 {%0,%1,%2,%3}, [%4];"
                 : "=r"(r[0]), "=r"(r[1]), "=r"(r[2]), "=r"(r[3]) : "r"(addr));
}
__device__ __forceinline__ void ldsm4t(uint32_t* r, uint32_t addr) {
    asm volatile("ldmatrix.sync.aligned.m8n8.x4.trans.shared.b16 {%0,%1,%2,%3}, [%4];"
                 : "=r"(r[0]), "=r"(r[1]), "=r"(r[2]), "=r"(r[3]) : "r"(addr));
}
__device__ __forceinline__ void mma16816(float* d, const uint32_t* a, const uint32_t* b) {
    asm volatile("mma.sync.aligned.m16n8k16.row.col.f32.f16.f16.f32 "
                 "{%0,%1,%2,%3}, {%4,%5,%6,%7}, {%8,%9}, {%0,%1,%2,%3};"
                 : "+f"(d[0]), "+f"(d[1]), "+f"(d[2]), "+f"(d[3])
                 : "r"(a[0]), "r"(a[1]), "r"(a[2]), "r"(a[3]), "r"(b[0]), "r"(b[1]));
}
__device__ __forceinline__ float ex2(float x) {
    float y;
    asm("ex2.approx.f32 %0, %1;" : "=f"(y) : "f"(x));
    return y;
}

// ============================================================
// LayerNorm -> fp16 output
// ============================================================
__global__ void __launch_bounds__(256) ln_kernel(const float* __restrict__ x,
                                                 const float* __restrict__ sc,
                                                 const float* __restrict__ bi,
                                                 __half* __restrict__ y) {
    const int row = blockIdx.x;
    const float* xr = x + (size_t)row * DM;
    float v[4];
    float s = 0.f, ss = 0.f;
#pragma unroll
    for (int i = 0; i < 4; i++) {
        v[i] = xr[threadIdx.x + 256 * i];
        s += v[i]; ss += v[i] * v[i];
    }
#pragma unroll
    for (int o = 16; o; o >>= 1) {
        s  += __shfl_xor_sync(0xffffffffu, s,  o);
        ss += __shfl_xor_sync(0xffffffffu, ss, o);
    }
    __shared__ float rs[8], rss[8];
    const int w = threadIdx.x >> 5, ln = threadIdx.x & 31;
    if (ln == 0) { rs[w] = s; rss[w] = ss; }
    __syncthreads();
    if (threadIdx.x == 0) {
        float ts = 0.f, tss = 0.f;
#pragma unroll
        for (int i = 0; i < 8; i++) { ts += rs[i]; tss += rss[i]; }
        rs[0] = ts; rss[0] = tss;
    }
    __syncthreads();
    const float mean = rs[0] * (1.f / DM);
    float var = rss[0] * (1.f / DM) - mean * mean;
    var = fmaxf(var, 0.f);
    const float inv = 1.f / (sqrtf(var) + 1e-5f);
#pragma unroll
    for (int i = 0; i < 4; i++) {
        const int c = threadIdx.x + 256 * i;
        y[(size_t)row * DM + c] = __float2half((v[i] - mean) * inv * sc[c] + bi[c]);
    }
}

// ============================================================
// Batched weight transpose + fp16 convert (all 6 weights, one launch)
// ============================================================
__global__ void __launch_bounds__(256) wtrans_all(
    const float* __restrict__ wq, const float* __restrict__ wk,
    const float* __restrict__ wv, const float* __restrict__ wo,
    const float* __restrict__ w1, const float* __restrict__ w2,
    __half* __restrict__ wqkvt, __half* __restrict__ wot,
    __half* __restrict__ w1t,   __half* __restrict__ w2t) {
    __shared__ float t[32][33];
    const int bid = blockIdx.x;
    const float* W; __half* Wt; int K, N, n0, k0;
    if (bid < 4096) {
        const int m  = bid >> 10;
        const int bb = bid & 1023;
        W  = (m == 0) ? wq : (m == 1) ? wk : (m == 2) ? wv : wo;
        Wt = (m == 3) ? wot : (wqkvt + (size_t)m * DM * DM);
        K = DM; N = DM;
        n0 = (bb & 31) << 5; k0 = (bb >> 5) << 5;
    } else if (bid < 8192) {
        const int bb = bid - 4096;
        W = w1; Wt = w1t; K = DM; N = DFFN;
        n0 = (bb & 127) << 5; k0 = (bb >> 7) << 5;
    } else {
        const int bb = bid - 8192;
        W = w2; Wt = w2t; K = DFFN; N = DM;
        n0 = (bb & 31) << 5; k0 = (bb >> 5) << 5;
    }
    const int tx = threadIdx.x & 31, ty = threadIdx.x >> 5;
#pragma unroll
    for (int i = 0; i < 4; i++)
        t[ty + 8 * i][tx] = W[(size_t)(k0 + ty + 8 * i) * N + n0 + tx];
    __syncthreads();
#pragma unroll
    for (int i = 0; i < 4; i++)
        Wt[(size_t)(n0 + ty + 8 * i) * K + k0 + tx] = __float2half(t[tx][ty + 8 * i]);
}

// ============================================================
// HMMA fp16 GEMM: C[M, N] = A[M,K] @ B[N,K]^T
// BM=BN=128, BK=64, 128 threads = 4 warps (2 M x 2 N), warp tile 64x64.
// 2-stage cp.async pipeline, 73.7KB smem -> 2 CTAs/SM.
// mode bits: 1=+bias, 2=+residual, 4=GELU. Cf!=null -> fp32 out, else fp16.
// ============================================================
#define RSTRIDE 144                    // bytes per smem row (64 halves + pad)
#define MATB    (128 * RSTRIDE)        // 18432 B per matrix tile
#define STAGEB  (2 * MATB)             // A, B

__global__ void __launch_bounds__(128) hgemm_kernel(
    const __half* __restrict__ A, const __half* __restrict__ B,
    const float* __restrict__ bias, const float* __restrict__ Rres,
    float* __restrict__ Cf, __half* __restrict__ Ch,
    int N, int K, int mode) {
    extern __shared__ char dsm[];
    const uint32_t sb = smem_u32(dsm);

    const int tid  = threadIdx.x;
    const int lane = tid & 31;
    const int wid  = tid >> 5;
    const int wm   = wid & 1;          // 2 M groups of 64
    const int wn   = wid >> 1;         // 2 N groups of 64
    const int brow = blockIdx.y << 7;
    const int bcol = blockIdx.x << 7;

    auto load_stage = [&](int c, int s) {
        const uint32_t st = sb + s * STAGEB;
        const size_t kb = (size_t)c << 6;
#pragma unroll
        for (int i = 0; i < 16; i++) {
            const int idx = tid + (i << 7);       // 0..2047
            const int r  = idx >> 3;              // 0..255 (A rows then B rows)
            const int ch = idx & 7;
            const uint32_t d = st + r * RSTRIDE + (ch << 4);
            const __half* src = (r < 128)
                ? (A + (size_t)(brow + r) * K + kb + (ch << 3))
                : (B + (size_t)(bcol + r - 128) * K + kb + (ch << 3));
            cp16(d, src);
        }
        asm volatile("cp.async.commit_group;" ::: "memory");
    };

    float acc[4][8][4];
#pragma unroll
    for (int mt = 0; mt < 4; mt++)
#pragma unroll
        for (int nt = 0; nt < 8; nt++)
#pragma unroll
            for (int e = 0; e < 4; e++) acc[mt][nt][e] = 0.f;

    load_stage(0, 0);

    const int NC = K >> 6;
    for (int c = 0; c < NC; c++) {
        const int s = c & 1;
        asm volatile("cp.async.wait_group 0;" ::: "memory");
        __syncthreads();
        if (c + 1 < NC) load_stage(c + 1, s ^ 1);

        const uint32_t st = sb + s * STAGEB;
#pragma unroll
        for (int kk = 0; kk < 4; kk++) {
            uint32_t Af[4][4], Bf[4][4];
#pragma unroll
            for (int mt = 0; mt < 4; mt++) {
                const int row  = (wm << 6) + (mt << 4) + (lane & 7) + (((lane >> 3) & 1) << 3);
                const int colh = (kk << 4) + ((lane >> 4) << 3);
                ldsm4(Af[mt], st + row * RSTRIDE + (colh << 1));
            }
#pragma unroll
            for (int p = 0; p < 4; p++) {
                const int row  = (wn << 6) + (p << 4) + (lane & 7) + ((lane >= 16) << 3);
                const int colh = (kk << 4) + (((lane >> 3) & 1) << 3);
                ldsm4(Bf[p], st + MATB + row * RSTRIDE + (colh << 1));
            }
#pragma unroll
            for (int mt = 0; mt < 4; mt++)
#pragma unroll
                for (int nt = 0; nt < 8; nt++)
                    mma16816(acc[mt][nt], Af[mt], &Bf[nt >> 1][(nt & 1) << 1]);
        }
        __syncthreads();
    }

    // ---------------- epilogue ----------------
    const int lr = lane >> 2;
    const int lc = (lane & 3) << 1;
#pragma unroll
    for (int mt = 0; mt < 4; mt++) {
#pragma unroll
        for (int h = 0; h < 2; h++) {
            const int row = brow + (wm << 6) + (mt << 4) + lr + (h << 3);
            const size_t crow = (size_t)row * N;
#pragma unroll
            for (int nt = 0; nt < 8; nt++) {
                const int col = bcol + (wn << 6) + (nt << 3) + lc;
                float v0 = acc[mt][nt][2 * h];
                float v1 = acc[mt][nt][2 * h + 1];
                if (mode & 1) {
                    const float2 bb = *(const float2*)&bias[col];
                    v0 += bb.x; v1 += bb.y;
                }
                if (mode & 4) {
                    v0 = 0.5f * v0 * (1.f + erff(v0 * 0.70710678118654752f));
                    v1 = 0.5f * v1 * (1.f + erff(v1 * 0.70710678118654752f));
                }
                if (mode & 2) {
                    const float2 rr = *(const float2*)&Rres[crow + col];
                    v0 += rr.x; v1 += rr.y;
                }
                if (Cf) {
                    float2 o; o.x = v0; o.y = v1;
                    *(float2*)&Cf[crow + col] = o;
                } else {
                    *(__half2*)&Ch[crow + col] = __floats2half2_rn(v0, v1);
                }
            }
        }
    }
}

// ============================================================
// Tensor-core causal flash attention (FA2-style), fp16 in/out.
// qkv: [B*T, 3072] fp16 (q | k | v column blocks).
// 8 warps, BQ=128 (16 rows/warp), BK=64, double-buffered K/V.
// Warps predicate off fully-masked diagonal tiles.
// 1/sqrt(DH) folded into the exp2 constant.
// ============================================================
#define LDQKV 3072
#define FQ  (128 * 144)                // 18432 B Q tile
#define FKV (64 * 144)                 // 9216 B per K/V buffer
#define FSMEM (FQ + 4 * FKV)           // 55296 B

__global__ void __launch_bounds__(256) flash_kernel(const __half* __restrict__ qkv,
                                                    __half* __restrict__ at) {
    extern __shared__ char fsm[];
    const uint32_t sbf = smem_u32(fsm);
    const uint32_t qb = sbf;
    const uint32_t kb = sbf + FQ;
    const uint32_t vb = sbf + FQ + 2 * FKV;

    const int tid  = threadIdx.x;
    const int lane = tid & 31;
    const int w    = tid >> 5;          // 0..7
    const int lr   = lane >> 2;
    const int lc   = (lane & 3) << 1;
    const int q0   = blockIdx.x << 7;   // BQ=128
    const int head = blockIdx.y;
    const int b    = blockIdx.z;
    const size_t base = ((size_t)b * SEQ) * LDQKV + head * DH;
    const float CE = 0.18033688011f;    // log2(e)/8
    const int wr = q0 + (w << 4);       // warp's first q row

    // load Q tile (128 rows x 8 chunks = 1024 cp16 over 256 threads)
#pragma unroll
    for (int i = 0; i < 4; i++) {
        const int idx = tid + (i << 8);
        const int r = idx >> 3, ch = idx & 7;
        cp16(qb + r * 144 + (ch << 4), qkv + base + (size_t)(q0 + r) * LDQKV + (ch << 3));
    }
    auto load_kv = [&](int kv0, int buf) {
#pragma unroll
        for (int i = 0; i < 2; i++) {
            const int idx = tid + (i << 8);       // 0..511
            const int r = idx >> 3, ch = idx & 7;
            const size_t g = base + (size_t)(kv0 + r) * LDQKV + (ch << 3);
            cp16(kb + buf * FKV + r * 144 + (ch << 4), qkv + 1024 + g);
            cp16(vb + buf * FKV + r * 144 + (ch << 4), qkv + 2048 + g);
        }
        asm volatile("cp.async.commit_group;" ::: "memory");
    };

    load_kv(0, 0);
    asm volatile("cp.async.wait_group 0;" ::: "memory");
    __syncthreads();

    float m[2] = {-1e30f, -1e30f}, l[2] = {0.f, 0.f};
    float o[8][4];
#pragma unroll
    for (int j = 0; j < 8; j++)
#pragma unroll
        for (int e = 0; e < 4; e++) o[j][e] = 0.f;

    const int iters = (q0 >> 6) + 2;
    for (int it = 0; it < iters; it++) {
        const int buf = it & 1;
        const int kv0 = it << 6;
        if (it + 1 < iters) load_kv((it + 1) << 6, buf ^ 1);

        if (kv0 <= wr + 15) {           // tile has unmasked cols for this warp
            float sacc[8][4];
#pragma unroll
            for (int j = 0; j < 8; j++)
#pragma unroll
                for (int e = 0; e < 4; e++) sacc[j][e] = 0.f;
#pragma unroll
            for (int kk = 0; kk < 4; kk++) {
                uint32_t af[4];
                {
                    const int row  = (w << 4) + (lane & 7) + (((lane >> 3) & 1) << 3);
                    const int colh = (kk << 4) + ((lane >> 4) << 3);
                    ldsm4(af, qb + row * 144 + (colh << 1));
                }
#pragma unroll
                for (int p = 0; p < 4; p++) {
                    uint32_t bf[4];
                    const int row  = (p << 4) + (lane & 7) + ((lane >= 16) << 3);
                    const int colh = (kk << 4) + (((lane >> 3) & 1) << 3);
                    ldsm4(bf, kb + buf * FKV + row * 144 + (colh << 1));
                    mma16816(sacc[2 * p],     af, &bf[0]);
                    mma16816(sacc[2 * p + 1], af, &bf[2]);
                }
            }

            if (kv0 + 63 > wr) {        // diagonal tile(s): apply causal mask
#pragma unroll
                for (int j = 0; j < 8; j++)
#pragma unroll
                    for (int e = 0; e < 4; e++) {
                        const int row = wr + lr + ((e >> 1) << 3);
                        const int col = kv0 + (j << 3) + lc + (e & 1);
                        if (col > row) sacc[j][e] = -1e30f;
                    }
            }

#pragma unroll
            for (int h = 0; h < 2; h++) {
                float mx = -1e30f;
#pragma unroll
                for (int j = 0; j < 8; j++)
                    mx = fmaxf(mx, fmaxf(sacc[j][2 * h], sacc[j][2 * h + 1]));
                mx = fmaxf(mx, __shfl_xor_sync(0xffffffffu, mx, 1));
                mx = fmaxf(mx, __shfl_xor_sync(0xffffffffu, mx, 2));
                const float mn = fmaxf(m[h], mx);
                const float alpha = ex2((m[h] - mn) * CE);
                m[h] = mn;
                float rsum = 0.f;
#pragma unroll
                for (int j = 0; j < 8; j++) {
                    sacc[j][2 * h]     = ex2((sacc[j][2 * h]     - mn) * CE);
                    sacc[j][2 * h + 1] = ex2((sacc[j][2 * h + 1] - mn) * CE);
                    rsum += sacc[j][2 * h] + sacc[j][2 * h + 1];
                }
                rsum += __shfl_xor_sync(0xffffffffu, rsum, 1);
                rsum += __shfl_xor_sync(0xffffffffu, rsum, 2);
                l[h] = l[h] * alpha + rsum;
#pragma unroll
                for (int j = 0; j < 8; j++) {
                    o[j][2 * h]     *= alpha;
                    o[j][2 * h + 1] *= alpha;
                }
            }

#pragma unroll
            for (int kk = 0; kk < 4; kk++) {
                uint32_t pa[4];
                {
                    __half2 t0 = __floats2half2_rn(sacc[2 * kk][0],     sacc[2 * kk][1]);
                    __half2 t1 = __floats2half2_rn(sacc[2 * kk][2],     sacc[2 * kk][3]);
                    __half2 t2 = __floats2half2_rn(sacc[2 * kk + 1][0], sacc[2 * kk + 1][1]);
                    __half2 t3 = __floats2half2_rn(sacc[2 * kk + 1][2], sacc[2 * kk + 1][3]);
                    pa[0] = *(uint32_t*)&t0; pa[1] = *(uint32_t*)&t1;
                    pa[2] = *(uint32_t*)&t2; pa[3] = *(uint32_t*)&t3;
                }
#pragma unroll
                for (int d = 0; d < 4; d++) {
                    uint32_t vf[4];
                    const int row  = (kk << 4) + (lane & 15);
                    const int colh = (d << 4) + ((lane >> 4) << 3);
                    ldsm4t(vf, vb + buf * FKV + row * 144 + (colh << 1));
                    mma16816(o[2 * d],     pa, &vf[0]);
                    mma16816(o[2 * d + 1], pa, &vf[2]);
                }
            }
        }

        asm volatile("cp.async.wait_group 0;" ::: "memory");
        __syncthreads();
    }

    const float inv0 = 1.f / l[0], inv1 = 1.f / l[1];
    const size_t obase = ((size_t)b * SEQ) * DM + head * DH;
#pragma unroll
    for (int j = 0; j < 8; j++) {
        const int col = (j << 3) + lc;
        const int r0 = wr + lr;
        *(__half2*)&at[obase + (size_t)r0 * DM + col] =
            __floats2half2_rn(o[j][0] * inv0, o[j][1] * inv0);
        *(__half2*)&at[obase + (size_t)(r0 + 8) * DM + col] =
            __floats2half2_rn(o[j][2] * inv1, o[j][3] * inv1);
    }
}

// ============================================================
// launch
// ============================================================
extern "C" void kernel_launch(void* const* d_in, const int* in_sizes, int n_in,
                              void* d_out, int out_size) {
    const float* x    = (const float*)d_in[0];
    const float* wq   = (const float*)d_in[1];
    const float* wk   = (const float*)d_in[2];
    const float* wv   = (const float*)d_in[3];
    const float* wo   = (const float*)d_in[4];
    const float* bo   = (const float*)d_in[5];
    const float* w1   = (const float*)d_in[6];
    const float* b1   = (const float*)d_in[7];
    const float* w2   = (const float*)d_in[8];
    const float* b2   = (const float*)d_in[9];
    const float* ln1s = (const float*)d_in[10];
    const float* ln1b = (const float*)d_in[11];
    const float* ln2s = (const float*)d_in[12];
    const float* ln2b = (const float*)d_in[13];
    float* out = (float*)d_out;

    __half *h, *qkv, *at, *h2, *ff;
    float* x1;
    __half *wqkvt, *wot, *w1t, *w2t;
    cudaGetSymbolAddress((void**)&h,     g_h);
    cudaGetSymbolAddress((void**)&qkv,   g_qkv);
    cudaGetSymbolAddress((void**)&at,    g_at);
    cudaGetSymbolAddress((void**)&x1,    g_x1);
    cudaGetSymbolAddress((void**)&h2,    g_h2);
    cudaGetSymbolAddress((void**)&ff,    g_ff);
    cudaGetSymbolAddress((void**)&wqkvt, g_wqkv);
    cudaGetSymbolAddress((void**)&wot,   g_wo);
    cudaGetSymbolAddress((void**)&w1t,   g_w1);
    cudaGetSymbolAddress((void**)&w2t,   g_w2);

    const int SMEM = 2 * STAGEB;   // 73728 bytes -> 2 CTAs/SM
    cudaFuncSetAttribute(hgemm_kernel, cudaFuncAttributeMaxDynamicSharedMemorySize, SMEM);
    cudaFuncSetAttribute(flash_kernel, cudaFuncAttributeMaxDynamicSharedMemorySize, FSMEM);

    // all weight transposes in one launch
    wtrans_all<<<12288, 256>>>(wq, wk, wv, wo, w1, w2, wqkvt, wot, w1t, w2t);

    // LN1 -> h (fp16)
    ln_kernel<<<BT, 256>>>(x, ln1s, ln1b, h);

    const dim3 gQKV(3 * DM / 128, BT / 128);
    const dim3 gD(DM / 128, BT / 128);
    const dim3 gF(DFFN / 128, BT / 128);
    const dim3 gAt(SEQ / 128, NH, 2);

    // fused QKV projection (fp16 out)
    hgemm_kernel<<<gQKV, 128, SMEM>>>(h, wqkvt, nullptr, nullptr,
                                      nullptr, qkv, 3 * DM, DM, 0);
    // tensor-core flash attention (fp16 out)
    flash_kernel<<<gAt, 256, FSMEM>>>(qkv, at);
    // out-proj + bias + residual -> x1 (fp32)
    hgemm_kernel<<<gD, 128, SMEM>>>(at, wot, bo, x, x1, nullptr, DM, DM, 1 | 2);
    // LN2 -> h2 (fp16)
    ln_kernel<<<BT, 256>>>(x1, ln2s, ln2b, h2);
    // FFN1 + bias + GELU -> ff (fp16)
    hgemm_kernel<<<gF, 128, SMEM>>>(h2, w1t, b1, nullptr, nullptr, ff, DFFN, DM, 1 | 4);
    // FFN2 + bias + residual -> out (fp32)
    hgemm_kernel<<<gD, 128, SMEM>>>(ff, w2t, b2, x1, out, nullptr, DM, DFFN, 1 | 2);
}

// round 9
// speedup vs baseline: 1.0285x; 1.0285x over previous
#include <cuda_runtime.h>
#include <cuda_fp16.h>
#include <math.h>
#include <stdint.h>

// Problem constants
#define BT   4096
#define DM   1024
#define DFFN 4096
#define SEQ  2048
#define NH   16
#define DH   64

// ---------------- scratch (device globals) ----------------
__device__ __half g_h  [BT * DM];
__device__ __half g_qkv[BT * 3 * DM];
__device__ __half g_at [BT * DM];
__device__ float  g_x1 [BT * DM];
__device__ __half g_h2 [BT * DM];
__device__ __half g_ff [BT * DFFN];
__device__ __half g_wqkv[3 * DM * DM];   // [3072,1024] (transposed, fp16)
__device__ __half g_wo [DM * DM];
__device__ __half g_w1 [DFFN * DM];      // [4096,1024]
__device__ __half g_w2 [DM * DFFN];      // [1024,4096]

// ---------------- PTX helpers (base sm_80+ PTX only) ----------------
__device__ __forceinline__ uint32_t smem_u32(const void* p) {
    return (uint32_t)__cvta_generic_to_shared(p);
}
__device__ __forceinline__ void cp16(uint32_t dst, const void* src) {
    asm volatile("cp.async.cg.shared.global [%0], [%1], 16;" :: "r"(dst), "l"(src));
}
__device__ __forceinline__ void ldsm4(uint32_t* r, uint32_t addr) {
    asm volatile("ldmatrix.sync.aligned.m8n8.x4.shared.b16 {%0,%1,%2,%3}, [%4];"
                 : "=r"(r[0]), "=r"(r[1]), "=r"(r[2]), "=r"(r[3]) : "r"(addr));
}
__device__ __forceinline__ void ldsm4t(uint32_t* r, uint32_t addr) {
    asm volatile("ldmatrix.sync.aligned.m8n8.x4.trans.shared.b16 {%0,%1,%2,%3}, [%4];"
                 : "=r"(r[0]), "=r"(r[1]), "=r"(r[2]), "=r"(r[3]) : "r"(addr));
}
__device__ __forceinline__ void mma16816(float* d, const uint32_t* a, const uint32_t* b) {
    asm volatile("mma.sync.aligned.m16n8k16.row.col.f32.f16.f16.f32 "
                 "{%0,%1,%2,%3}, {%4,%5,%6,%7}, {%8,%9}, {%0,%1,%2,%3};"
                 : "+f"(d[0]), "+f"(d[1]), "+f"(d[2]), "+f"(d[3])
                 : "r"(a[0]), "r"(a[1]), "r"(a[2]), "r"(a[3]), "r"(b[0]), "r"(b[1]));
}
__device__ __forceinline__ float ex2(float x) {
    float y;
    asm("ex2.approx.f32 %0, %1;" : "=f"(y) : "f"(x));
    return y;
}

// ============================================================
// LayerNorm -> fp16 output
// ============================================================
__global__ void __launch_bounds__(256) ln_kernel(const float* __restrict__ x,
                                                 const float* __restrict__ sc,
                                                 const float* __restrict__ bi,
                                                 __half* __restrict__ y) {
    const int row = blockIdx.x;
    const float* xr = x + (size_t)row * DM;
    float v[4];
    float s = 0.f, ss = 0.f;
#pragma unroll
    for (int i = 0; i < 4; i++) {
        v[i] = xr[threadIdx.x + 256 * i];
        s += v[i]; ss += v[i] * v[i];
    }
#pragma unroll
    for (int o = 16; o; o >>= 1) {
        s  += __shfl_xor_sync(0xffffffffu, s,  o);
        ss += __shfl_xor_sync(0xffffffffu, ss, o);
    }
    __shared__ float rs[8], rss[8];
    const int w = threadIdx.x >> 5, ln = threadIdx.x & 31;
    if (ln == 0) { rs[w] = s; rss[w] = ss; }
    __syncthreads();
    if (threadIdx.x == 0) {
        float ts = 0.f, tss = 0.f;
#pragma unroll
        for (int i = 0; i < 8; i++) { ts += rs[i]; tss += rss[i]; }
        rs[0] = ts; rss[0] = tss;
    }
    __syncthreads();
    const float mean = rs[0] * (1.f / DM);
    float var = rss[0] * (1.f / DM) - mean * mean;
    var = fmaxf(var, 0.f);
    const float inv = 1.f / (sqrtf(var) + 1e-5f);
#pragma unroll
    for (int i = 0; i < 4; i++) {
        const int c = threadIdx.x + 256 * i;
        y[(size_t)row * DM + c] = __float2half((v[i] - mean) * inv * sc[c] + bi[c]);
    }
}

// ============================================================
// Batched weight transpose + fp16 convert (all 6 weights, one launch)
// ============================================================
__global__ void __launch_bounds__(256) wtrans_all(
    const float* __restrict__ wq, const float* __restrict__ wk,
    const float* __restrict__ wv, const float* __restrict__ wo,
    const float* __restrict__ w1, const float* __restrict__ w2,
    __half* __restrict__ wqkvt, __half* __restrict__ wot,
    __half* __restrict__ w1t,   __half* __restrict__ w2t) {
    __shared__ float t[32][33];
    const int bid = blockIdx.x;
    const float* W; __half* Wt; int K, N, n0, k0;
    if (bid < 4096) {
        const int m  = bid >> 10;
        const int bb = bid & 1023;
        W  = (m == 0) ? wq : (m == 1) ? wk : (m == 2) ? wv : wo;
        Wt = (m == 3) ? wot : (wqkvt + (size_t)m * DM * DM);
        K = DM; N = DM;
        n0 = (bb & 31) << 5; k0 = (bb >> 5) << 5;
    } else if (bid < 8192) {
        const int bb = bid - 4096;
        W = w1; Wt = w1t; K = DM; N = DFFN;
        n0 = (bb & 127) << 5; k0 = (bb >> 7) << 5;
    } else {
        const int bb = bid - 8192;
        W = w2; Wt = w2t; K = DFFN; N = DM;
        n0 = (bb & 31) << 5; k0 = (bb >> 5) << 5;
    }
    const int tx = threadIdx.x & 31, ty = threadIdx.x >> 5;
#pragma unroll
    for (int i = 0; i < 4; i++)
        t[ty + 8 * i][tx] = W[(size_t)(k0 + ty + 8 * i) * N + n0 + tx];
    __syncthreads();
#pragma unroll
    for (int i = 0; i < 4; i++)
        Wt[(size_t)(n0 + ty + 8 * i) * K + k0 + tx] = __float2half(t[tx][ty + 8 * i]);
}

// ============================================================
// HMMA fp16 GEMM: C[M, N] = A[M,K] @ B[N,K]^T  (R7-proven shape)
// BM=BN=128, BK=64, 256 threads = 8 warps (2 M x 4 N), warp tile 64x32.
// 2-stage cp.async pipeline, 73.7KB smem -> 2 CTAs/SM.
// mode bits: 1=+bias, 2=+residual, 4=GELU. Cf!=null -> fp32 out, else fp16.
// ============================================================
#define RSTRIDE 144                    // bytes per smem row (64 halves + pad)
#define MATB    (128 * RSTRIDE)        // 18432 B per matrix tile
#define STAGEB  (2 * MATB)             // A, B

__global__ void __launch_bounds__(256, 2) hgemm_kernel(
    const __half* __restrict__ A, const __half* __restrict__ B,
    const float* __restrict__ bias, const float* __restrict__ Rres,
    float* __restrict__ Cf, __half* __restrict__ Ch,
    int N, int K, int mode) {
    extern __shared__ char dsm[];
    const uint32_t sb = smem_u32(dsm);

    const int tid  = threadIdx.x;
    const int lane = tid & 31;
    const int wid  = tid >> 5;
    const int wm   = wid & 1;
    const int wn   = wid >> 1;
    const int brow = blockIdx.y << 7;
    const int bcol = blockIdx.x << 7;

    auto load_stage = [&](int c, int s) {
        const uint32_t st = sb + s * STAGEB;
        const size_t kb = (size_t)c << 6;
#pragma unroll
        for (int i = 0; i < 4; i++) {
            const int idx = tid + (i << 8);
            const int r  = idx >> 3;
            const int ch = idx & 7;
            const uint32_t d = st + r * RSTRIDE + (ch << 4);
            cp16(d,        A + (size_t)(brow + r) * K + kb + (ch << 3));
            cp16(d + MATB, B + (size_t)(bcol + r) * K + kb + (ch << 3));
        }
        asm volatile("cp.async.commit_group;" ::: "memory");
    };

    float acc[4][4][4];
#pragma unroll
    for (int mt = 0; mt < 4; mt++)
#pragma unroll
        for (int nt = 0; nt < 4; nt++)
#pragma unroll
            for (int e = 0; e < 4; e++) acc[mt][nt][e] = 0.f;

    load_stage(0, 0);

    const int NC = K >> 6;
    for (int c = 0; c < NC; c++) {
        const int s = c & 1;
        asm volatile("cp.async.wait_group 0;" ::: "memory");
        __syncthreads();
        if (c + 1 < NC) load_stage(c + 1, s ^ 1);

        const uint32_t st = sb + s * STAGEB;
#pragma unroll
        for (int kk = 0; kk < 4; kk++) {
            uint32_t Af[4][4], Bf[2][4];
#pragma unroll
            for (int mt = 0; mt < 4; mt++) {
                const int row  = (wm << 6) + (mt << 4) + (lane & 7) + (((lane >> 3) & 1) << 3);
                const int colh = (kk << 4) + ((lane >> 4) << 3);
                ldsm4(Af[mt], st + row * RSTRIDE + (colh << 1));
            }
#pragma unroll
            for (int p = 0; p < 2; p++) {
                const int row  = (wn << 5) + (p << 4) + (lane & 7) + ((lane >= 16) << 3);
                const int colh = (kk << 4) + (((lane >> 3) & 1) << 3);
                ldsm4(Bf[p], st + MATB + row * RSTRIDE + (colh << 1));
            }
#pragma unroll
            for (int mt = 0; mt < 4; mt++)
#pragma unroll
                for (int nt = 0; nt < 4; nt++)
                    mma16816(acc[mt][nt], Af[mt], &Bf[nt >> 1][(nt & 1) << 1]);
        }
        __syncthreads();
    }

    // ---------------- epilogue ----------------
    const int lr = lane >> 2;
    const int lc = (lane & 3) << 1;
#pragma unroll
    for (int mt = 0; mt < 4; mt++) {
#pragma unroll
        for (int h = 0; h < 2; h++) {
            const int row = brow + (wm << 6) + (mt << 4) + lr + (h << 3);
            const size_t crow = (size_t)row * N;
#pragma unroll
            for (int nt = 0; nt < 4; nt++) {
                const int col = bcol + (wn << 5) + (nt << 3) + lc;
                float v0 = acc[mt][nt][2 * h];
                float v1 = acc[mt][nt][2 * h + 1];
                if (mode & 1) {
                    const float2 bb = *(const float2*)&bias[col];
                    v0 += bb.x; v1 += bb.y;
                }
                if (mode & 4) {
                    v0 = 0.5f * v0 * (1.f + erff(v0 * 0.70710678118654752f));
                    v1 = 0.5f * v1 * (1.f + erff(v1 * 0.70710678118654752f));
                }
                if (mode & 2) {
                    const float2 rr = *(const float2*)&Rres[crow + col];
                    v0 += rr.x; v1 += rr.y;
                }
                if (Cf) {
                    float2 o; o.x = v0; o.y = v1;
                    *(float2*)&Cf[crow + col] = o;
                } else {
                    *(__half2*)&Ch[crow + col] = __floats2half2_rn(v0, v1);
                }
            }
        }
    }
}

// ============================================================
// Tensor-core causal flash attention (FA2-style), fp16 in/out.
// qkv: [B*T, 3072] fp16 (q | k | v column blocks).
// 8 warps, BQ=128 (16 rows/warp), BK=64, double-buffered K/V.
// Warps predicate off fully-masked diagonal tiles.
// 1/sqrt(DH) folded into the exp2 constant.
// ============================================================
#define LDQKV 3072
#define FQ  (128 * 144)                // 18432 B Q tile
#define FKV (64 * 144)                 // 9216 B per K/V buffer
#define FSMEM (FQ + 4 * FKV)           // 55296 B

__global__ void __launch_bounds__(256) flash_kernel(const __half* __restrict__ qkv,
                                                    __half* __restrict__ at) {
    extern __shared__ char fsm[];
    const uint32_t sbf = smem_u32(fsm);
    const uint32_t qb = sbf;
    const uint32_t kb = sbf + FQ;
    const uint32_t vb = sbf + FQ + 2 * FKV;

    const int tid  = threadIdx.x;
    const int lane = tid & 31;
    const int w    = tid >> 5;          // 0..7
    const int lr   = lane >> 2;
    const int lc   = (lane & 3) << 1;
    const int q0   = blockIdx.x << 7;   // BQ=128
    const int head = blockIdx.y;
    const int b    = blockIdx.z;
    const size_t base = ((size_t)b * SEQ) * LDQKV + head * DH;
    const float CE = 0.18033688011f;    // log2(e)/8
    const int wr = q0 + (w << 4);       // warp's first q row

    // load Q tile
#pragma unroll
    for (int i = 0; i < 4; i++) {
        const int idx = tid + (i << 8);
        const int r = idx >> 3, ch = idx & 7;
        cp16(qb + r * 144 + (ch << 4), qkv + base + (size_t)(q0 + r) * LDQKV + (ch << 3));
    }
    auto load_kv = [&](int kv0, int buf) {
#pragma unroll
        for (int i = 0; i < 2; i++) {
            const int idx = tid + (i << 8);
            const int r = idx >> 3, ch = idx & 7;
            const size_t g = base + (size_t)(kv0 + r) * LDQKV + (ch << 3);
            cp16(kb + buf * FKV + r * 144 + (ch << 4), qkv + 1024 + g);
            cp16(vb + buf * FKV + r * 144 + (ch << 4), qkv + 2048 + g);
        }
        asm volatile("cp.async.commit_group;" ::: "memory");
    };

    load_kv(0, 0);
    asm volatile("cp.async.wait_group 0;" ::: "memory");
    __syncthreads();

    float m[2] = {-1e30f, -1e30f}, l[2] = {0.f, 0.f};
    float o[8][4];
#pragma unroll
    for (int j = 0; j < 8; j++)
#pragma unroll
        for (int e = 0; e < 4; e++) o[j][e] = 0.f;

    const int iters = (q0 >> 6) + 2;
    for (int it = 0; it < iters; it++) {
        const int buf = it & 1;
        const int kv0 = it << 6;
        if (it + 1 < iters) load_kv((it + 1) << 6, buf ^ 1);

        if (kv0 <= wr + 15) {
            float sacc[8][4];
#pragma unroll
            for (int j = 0; j < 8; j++)
#pragma unroll
                for (int e = 0; e < 4; e++) sacc[j][e] = 0.f;
#pragma unroll
            for (int kk = 0; kk < 4; kk++) {
                uint32_t af[4];
                {
                    const int row  = (w << 4) + (lane & 7) + (((lane >> 3) & 1) << 3);
                    const int colh = (kk << 4) + ((lane >> 4) << 3);
                    ldsm4(af, qb + row * 144 + (colh << 1));
                }
#pragma unroll
                for (int p = 0; p < 4; p++) {
                    uint32_t bf[4];
                    const int row  = (p << 4) + (lane & 7) + ((lane >= 16) << 3);
                    const int colh = (kk << 4) + (((lane >> 3) & 1) << 3);
                    ldsm4(bf, kb + buf * FKV + row * 144 + (colh << 1));
                    mma16816(sacc[2 * p],     af, &bf[0]);
                    mma16816(sacc[2 * p + 1], af, &bf[2]);
                }
            }

            if (kv0 + 63 > wr) {
#pragma unroll
                for (int j = 0; j < 8; j++)
#pragma unroll
                    for (int e = 0; e < 4; e++) {
                        const int row = wr + lr + ((e >> 1) << 3);
                        const int col = kv0 + (j << 3) + lc + (e & 1);
                        if (col > row) sacc[j][e] = -1e30f;
                    }
            }

#pragma unroll
            for (int h = 0; h < 2; h++) {
                float mx = -1e30f;
#pragma unroll
                for (int j = 0; j < 8; j++)
                    mx = fmaxf(mx, fmaxf(sacc[j][2 * h], sacc[j][2 * h + 1]));
                mx = fmaxf(mx, __shfl_xor_sync(0xffffffffu, mx, 1));
                mx = fmaxf(mx, __shfl_xor_sync(0xffffffffu, mx, 2));
                const float mn = fmaxf(m[h], mx);
                const float alpha = ex2((m[h] - mn) * CE);
                m[h] = mn;
                float rsum = 0.f;
#pragma unroll
                for (int j = 0; j < 8; j++) {
                    sacc[j][2 * h]     = ex2((sacc[j][2 * h]     - mn) * CE);
                    sacc[j][2 * h + 1] = ex2((sacc[j][2 * h + 1] - mn) * CE);
                    rsum += sacc[j][2 * h] + sacc[j][2 * h + 1];
                }
                rsum += __shfl_xor_sync(0xffffffffu, rsum, 1);
                rsum += __shfl_xor_sync(0xffffffffu, rsum, 2);
                l[h] = l[h] * alpha + rsum;
#pragma unroll
                for (int j = 0; j < 8; j++) {
                    o[j][2 * h]     *= alpha;
                    o[j][2 * h + 1] *= alpha;
                }
            }

#pragma unroll
            for (int kk = 0; kk < 4; kk++) {
                uint32_t pa[4];
                {
                    __half2 t0 = __floats2half2_rn(sacc[2 * kk][0],     sacc[2 * kk][1]);
                    __half2 t1 = __floats2half2_rn(sacc[2 * kk][2],     sacc[2 * kk][3]);
                    __half2 t2 = __floats2half2_rn(sacc[2 * kk + 1][0], sacc[2 * kk + 1][1]);
                    __half2 t3 = __floats2half2_rn(sacc[2 * kk + 1][2], sacc[2 * kk + 1][3]);
                    pa[0] = *(uint32_t*)&t0; pa[1] = *(uint32_t*)&t1;
                    pa[2] = *(uint32_t*)&t2; pa[3] = *(uint32_t*)&t3;
                }
#pragma unroll
                for (int d = 0; d < 4; d++) {
                    uint32_t vf[4];
                    const int row  = (kk << 4) + (lane & 15);
                    const int colh = (d << 4) + ((lane >> 4) << 3);
                    ldsm4t(vf, vb + buf * FKV + row * 144 + (colh << 1));
                    mma16816(o[2 * d],     pa, &vf[0]);
                    mma16816(o[2 * d + 1], pa, &vf[2]);
                }
            }
        }

        asm volatile("cp.async.wait_group 0;" ::: "memory");
        __syncthreads();
    }

    const float inv0 = 1.f / l[0], inv1 = 1.f / l[1];
    const size_t obase = ((size_t)b * SEQ) * DM + head * DH;
#pragma unroll
    for (int j = 0; j < 8; j++) {
        const int col = (j << 3) + lc;
        const int r0 = wr + lr;
        *(__half2*)&at[obase + (size_t)r0 * DM + col] =
            __floats2half2_rn(o[j][0] * inv0, o[j][1] * inv0);
        *(__half2*)&at[obase + (size_t)(r0 + 8) * DM + col] =
            __floats2half2_rn(o[j][2] * inv1, o[j][3] * inv1);
    }
}

// ============================================================
// launch
// ============================================================
extern "C" void kernel_launch(void* const* d_in, const int* in_sizes, int n_in,
                              void* d_out, int out_size) {
    const float* x    = (const float*)d_in[0];
    const float* wq   = (const float*)d_in[1];
    const float* wk   = (const float*)d_in[2];
    const float* wv   = (const float*)d_in[3];
    const float* wo   = (const float*)d_in[4];
    const float* bo   = (const float*)d_in[5];
    const float* w1   = (const float*)d_in[6];
    const float* b1   = (const float*)d_in[7];
    const float* w2   = (const float*)d_in[8];
    const float* b2   = (const float*)d_in[9];
    const float* ln1s = (const float*)d_in[10];
    const float* ln1b = (const float*)d_in[11];
    const float* ln2s = (const float*)d_in[12];
    const float* ln2b = (const float*)d_in[13];
    float* out = (float*)d_out;

    __half *h, *qkv, *at, *h2, *ff;
    float* x1;
    __half *wqkvt, *wot, *w1t, *w2t;
    cudaGetSymbolAddress((void**)&h,     g_h);
    cudaGetSymbolAddress((void**)&qkv,   g_qkv);
    cudaGetSymbolAddress((void**)&at,    g_at);
    cudaGetSymbolAddress((void**)&x1,    g_x1);
    cudaGetSymbolAddress((void**)&h2,    g_h2);
    cudaGetSymbolAddress((void**)&ff,    g_ff);
    cudaGetSymbolAddress((void**)&wqkvt, g_wqkv);
    cudaGetSymbolAddress((void**)&wot,   g_wo);
    cudaGetSymbolAddress((void**)&w1t,   g_w1);
    cudaGetSymbolAddress((void**)&w2t,   g_w2);

    const int SMEM = 2 * STAGEB;   // 73728 bytes -> 2 CTAs/SM
    cudaFuncSetAttribute(hgemm_kernel, cudaFuncAttributeMaxDynamicSharedMemorySize, SMEM);
    cudaFuncSetAttribute(flash_kernel, cudaFuncAttributeMaxDynamicSharedMemorySize, FSMEM);

    // all weight transposes in one launch
    wtrans_all<<<12288, 256>>>(wq, wk, wv, wo, w1, w2, wqkvt, wot, w1t, w2t);

    // LN1 -> h (fp16)
    ln_kernel<<<BT, 256>>>(x, ln1s, ln1b, h);

    const dim3 gQKV(3 * DM / 128, BT / 128);
    const dim3 gD(DM / 128, BT / 128);
    const dim3 gF(DFFN / 128, BT / 128);
    const dim3 gAt(SEQ / 128, NH, 2);

    // fused QKV projection (fp16 out)
    hgemm_kernel<<<gQKV, 256, SMEM>>>(h, wqkvt, nullptr, nullptr,
                                      nullptr, qkv, 3 * DM, DM, 0);
    // tensor-core flash attention (fp16 out)
    flash_kernel<<<gAt, 256, FSMEM>>>(qkv, at);
    // out-proj + bias + residual -> x1 (fp32)
    hgemm_kernel<<<gD, 256, SMEM>>>(at, wot, bo, x, x1, nullptr, DM, DM, 1 | 2);
    // LN2 -> h2 (fp16)
    ln_kernel<<<BT, 256>>>(x1, ln2s, ln2b, h2);
    // FFN1 + bias + GELU -> ff (fp16)
    hgemm_kernel<<<gF, 256, SMEM>>>(h2, w1t, b1, nullptr, nullptr, ff, DFFN, DM, 1 | 4);
    // FFN2 + bias + residual -> out (fp32)
    hgemm_kernel<<<gD, 256, SMEM>>>(ff, w2t, b2, x1, out, nullptr, DM, DFFN, 1 | 2);
}

// round 12
// speedup vs baseline: 1.0467x; 1.0177x over previous
#include <cuda_runtime.h>
#include <cuda_fp16.h>
#include <math.h>
#include <stdint.h>

// Problem constants
#define BT   4096
#define DM   1024
#define DFFN 4096
#define SEQ  2048
#define NH   16
#define DH   64

// ---------------- scratch (device globals) ----------------
__device__ __half g_h  [BT * DM];
__device__ __half g_qkv[BT * 3 * DM];
__device__ __half g_at [BT * DM];
__device__ float  g_x1 [BT * DM];
__device__ __half g_h2 [BT * DM];
__device__ __half g_ff [BT * DFFN];
__device__ __half g_wqkv[3 * DM * DM];   // [3072,1024] (transposed, fp16)
__device__ __half g_wo [DM * DM];
__device__ __half g_w1 [DFFN * DM];      // [4096,1024]
__device__ __half g_w2 [DM * DFFN];      // [1024,4096]

// ---------------- PTX helpers (base sm_80+ PTX only) ----------------
__device__ __forceinline__ uint32_t smem_u32(const void* p) {
    return (uint32_t)__cvta_generic_to_shared(p);
}
__device__ __forceinline__ void cp16(uint32_t dst, const void* src) {
    asm volatile("cp.async.cg.shared.global [%0], [%1], 16;" :: "r"(dst), "l"(src));
}
__device__ __forceinline__ void ldsm4(uint32_t* r, uint32_t addr) {
    asm volatile("ldmatrix.sync.aligned.m8n8.x4.shared.b16 {%0,%1,%2,%3}, [%4];"
                 : "=r"(r[0]), "=r"(r[1]), "=r"(r[2]), "=r"(r[3]) : "r"(addr));
}
__device__ __forceinline__ void ldsm4t(uint32_t* r, uint32_t addr) {
    asm volatile("ldmatrix.sync.aligned.m8n8.x4.trans.shared.b16 {%0,%1,%2,%3}, [%4];"
                 : "=r"(r[0]), "=r"(r[1]), "=r"(r[2]), "=r"(r[3]) : "r"(addr));
}
__device__ __forceinline__ void mma16816(float* d, const uint32_t* a, const uint32_t* b) {
    asm volatile("mma.sync.aligned.m16n8k16.row.col.f32.f16.f16.f32 "
                 "{%0,%1,%2,%3}, {%4,%5,%6,%7}, {%8,%9}, {%0,%1,%2,%3};"
                 : "+f"(d[0]), "+f"(d[1]), "+f"(d[2]), "+f"(d[3])
                 : "r"(a[0]), "r"(a[1]), "r"(a[2]), "r"(a[3]), "r"(b[0]), "r"(b[1]));
}
__device__ __forceinline__ float ex2(float x) {
    float y;
    asm("ex2.approx.f32 %0, %1;" : "=f"(y) : "f"(x));
    return y;
}

// ============================================================
// LayerNorm -> fp16 output
// ============================================================
__global__ void __launch_bounds__(256) ln_kernel(const float* __restrict__ x,
                                                 const float* __restrict__ sc,
                                                 const float* __restrict__ bi,
                                                 __half* __restrict__ y) {
    const int row = blockIdx.x;
    const float* xr = x + (size_t)row * DM;
    float v[4];
    float s = 0.f, ss = 0.f;
#pragma unroll
    for (int i = 0; i < 4; i++) {
        v[i] = xr[threadIdx.x + 256 * i];
        s += v[i]; ss += v[i] * v[i];
    }
#pragma unroll
    for (int o = 16; o; o >>= 1) {
        s  += __shfl_xor_sync(0xffffffffu, s,  o);
        ss += __shfl_xor_sync(0xffffffffu, ss, o);
    }
    __shared__ float rs[8], rss[8];
    const int w = threadIdx.x >> 5, ln = threadIdx.x & 31;
    if (ln == 0) { rs[w] = s; rss[w] = ss; }
    __syncthreads();
    if (threadIdx.x == 0) {
        float ts = 0.f, tss = 0.f;
#pragma unroll
        for (int i = 0; i < 8; i++) { ts += rs[i]; tss += rss[i]; }
        rs[0] = ts; rss[0] = tss;
    }
    __syncthreads();
    const float mean = rs[0] * (1.f / DM);
    float var = rss[0] * (1.f / DM) - mean * mean;
    var = fmaxf(var, 0.f);
    const float inv = 1.f / (sqrtf(var) + 1e-5f);
#pragma unroll
    for (int i = 0; i < 4; i++) {
        const int c = threadIdx.x + 256 * i;
        y[(size_t)row * DM + c] = __float2half((v[i] - mean) * inv * sc[c] + bi[c]);
    }
}

// ============================================================
// Batched weight transpose + fp16 convert (all 6 weights, one launch)
// ============================================================
__global__ void __launch_bounds__(256) wtrans_all(
    const float* __restrict__ wq, const float* __restrict__ wk,
    const float* __restrict__ wv, const float* __restrict__ wo,
    const float* __restrict__ w1, const float* __restrict__ w2,
    __half* __restrict__ wqkvt, __half* __restrict__ wot,
    __half* __restrict__ w1t,   __half* __restrict__ w2t) {
    __shared__ float t[32][33];
    const int bid = blockIdx.x;
    const float* W; __half* Wt; int K, N, n0, k0;
    if (bid < 4096) {
        const int m  = bid >> 10;
        const int bb = bid & 1023;
        W  = (m == 0) ? wq : (m == 1) ? wk : (m == 2) ? wv : wo;
        Wt = (m == 3) ? wot : (wqkvt + (size_t)m * DM * DM);
        K = DM; N = DM;
        n0 = (bb & 31) << 5; k0 = (bb >> 5) << 5;
    } else if (bid < 8192) {
        const int bb = bid - 4096;
        W = w1; Wt = w1t; K = DM; N = DFFN;
        n0 = (bb & 127) << 5; k0 = (bb >> 7) << 5;
    } else {
        const int bb = bid - 8192;
        W = w2; Wt = w2t; K = DFFN; N = DM;
        n0 = (bb & 31) << 5; k0 = (bb >> 5) << 5;
    }
    const int tx = threadIdx.x & 31, ty = threadIdx.x >> 5;
#pragma unroll
    for (int i = 0; i < 4; i++)
        t[ty + 8 * i][tx] = W[(size_t)(k0 + ty + 8 * i) * N + n0 + tx];
    __syncthreads();
#pragma unroll
    for (int i = 0; i < 4; i++)
        Wt[(size_t)(n0 + ty + 8 * i) * K + k0 + tx] = __float2half(t[tx][ty + 8 * i]);
}

// ============================================================
// HMMA fp16 GEMM: C[M, N] = A[M,K] @ B[N,K]^T  (R7-proven shape)
// BM=BN=128, BK=64, 256 threads = 8 warps (2 M x 4 N), warp tile 64x32.
// 2-stage cp.async, prefetch issued BEFORE wait (depth-2 pipeline).
// 73.7KB smem -> 2 CTAs/SM.
// mode bits: 1=+bias, 2=+residual, 4=GELU. Cf!=null -> fp32 out, else fp16.
// ============================================================
#define RSTRIDE 144                    // bytes per smem row (64 halves + pad)
#define MATB    (128 * RSTRIDE)        // 18432 B per matrix tile
#define STAGEB  (2 * MATB)             // A, B

__global__ void __launch_bounds__(256, 2) hgemm_kernel(
    const __half* __restrict__ A, const __half* __restrict__ B,
    const float* __restrict__ bias, const float* __restrict__ Rres,
    float* __restrict__ Cf, __half* __restrict__ Ch,
    int N, int K, int mode) {
    extern __shared__ char dsm[];
    const uint32_t sb = smem_u32(dsm);

    const int tid  = threadIdx.x;
    const int lane = tid & 31;
    const int wid  = tid >> 5;
    const int wm   = wid & 1;
    const int wn   = wid >> 1;
    const int brow = blockIdx.y << 7;
    const int bcol = blockIdx.x << 7;

    auto load_stage = [&](int c, int s) {
        const uint32_t st = sb + s * STAGEB;
        const size_t kb = (size_t)c << 6;
#pragma unroll
        for (int i = 0; i < 4; i++) {
            const int idx = tid + (i << 8);
            const int r  = idx >> 3;
            const int ch = idx & 7;
            const uint32_t d = st + r * RSTRIDE + (ch << 4);
            cp16(d,        A + (size_t)(brow + r) * K + kb + (ch << 3));
            cp16(d + MATB, B + (size_t)(bcol + r) * K + kb + (ch << 3));
        }
        asm volatile("cp.async.commit_group;" ::: "memory");
    };

    float acc[4][4][4];
#pragma unroll
    for (int mt = 0; mt < 4; mt++)
#pragma unroll
        for (int nt = 0; nt < 4; nt++)
#pragma unroll
            for (int e = 0; e < 4; e++) acc[mt][nt][e] = 0.f;

    load_stage(0, 0);

    const int NC = K >> 6;
    for (int c = 0; c < NC; c++) {
        const int s = c & 1;
        // issue next chunk BEFORE waiting on current (stage s^1 was consumed
        // before the trailing __syncthreads of iter c-1)
        if (c + 1 < NC) {
            load_stage(c + 1, s ^ 1);
            asm volatile("cp.async.wait_group 1;" ::: "memory");
        } else {
            asm volatile("cp.async.wait_group 0;" ::: "memory");
        }
        __syncthreads();

        const uint32_t st = sb + s * STAGEB;
#pragma unroll
        for (int kk = 0; kk < 4; kk++) {
            uint32_t Af[4][4], Bf[2][4];
#pragma unroll
            for (int mt = 0; mt < 4; mt++) {
                const int row  = (wm << 6) + (mt << 4) + (lane & 7) + (((lane >> 3) & 1) << 3);
                const int colh = (kk << 4) + ((lane >> 4) << 3);
                ldsm4(Af[mt], st + row * RSTRIDE + (colh << 1));
            }
#pragma unroll
            for (int p = 0; p < 2; p++) {
                const int row  = (wn << 5) + (p << 4) + (lane & 7) + ((lane >= 16) << 3);
                const int colh = (kk << 4) + (((lane >> 3) & 1) << 3);
                ldsm4(Bf[p], st + MATB + row * RSTRIDE + (colh << 1));
            }
#pragma unroll
            for (int mt = 0; mt < 4; mt++)
#pragma unroll
                for (int nt = 0; nt < 4; nt++)
                    mma16816(acc[mt][nt], Af[mt], &Bf[nt >> 1][(nt & 1) << 1]);
        }
        __syncthreads();
    }

    // ---------------- epilogue ----------------
    const int lr = lane >> 2;
    const int lc = (lane & 3) << 1;
#pragma unroll
    for (int mt = 0; mt < 4; mt++) {
#pragma unroll
        for (int h = 0; h < 2; h++) {
            const int row = brow + (wm << 6) + (mt << 4) + lr + (h << 3);
            const size_t crow = (size_t)row * N;
#pragma unroll
            for (int nt = 0; nt < 4; nt++) {
                const int col = bcol + (wn << 5) + (nt << 3) + lc;
                float v0 = acc[mt][nt][2 * h];
                float v1 = acc[mt][nt][2 * h + 1];
                if (mode & 1) {
                    const float2 bb = *(const float2*)&bias[col];
                    v0 += bb.x; v1 += bb.y;
                }
                if (mode & 4) {
                    v0 = 0.5f * v0 * (1.f + erff(v0 * 0.70710678118654752f));
                    v1 = 0.5f * v1 * (1.f + erff(v1 * 0.70710678118654752f));
                }
                if (mode & 2) {
                    const float2 rr = *(const float2*)&Rres[crow + col];
                    v0 += rr.x; v1 += rr.y;
                }
                if (Cf) {
                    float2 o; o.x = v0; o.y = v1;
                    *(float2*)&Cf[crow + col] = o;
                } else {
                    *(__half2*)&Ch[crow + col] = __floats2half2_rn(v0, v1);
                }
            }
        }
    }
}

// ============================================================
// Tensor-core causal flash attention (FA2-style), fp16 in/out.
// qkv: [B*T, 3072] fp16 (q | k | v column blocks).
// 8 warps, BQ=128 (16 rows/warp), BK=64, double-buffered K/V.
// Heavy q-tiles scheduled FIRST (blockIdx.x reversed) for tail balance.
// Warps predicate off fully-masked diagonal tiles.
// 1/sqrt(DH) folded into the exp2 constant.
// ============================================================
#define LDQKV 3072
#define FQ  (128 * 144)                // 18432 B Q tile
#define FKV (64 * 144)                 // 9216 B per K/V buffer
#define FSMEM (FQ + 4 * FKV)           // 55296 B

__global__ void __launch_bounds__(256) flash_kernel(const __half* __restrict__ qkv,
                                                    __half* __restrict__ at) {
    extern __shared__ char fsm[];
    const uint32_t sbf = smem_u32(fsm);
    const uint32_t qb = sbf;
    const uint32_t kb = sbf + FQ;
    const uint32_t vb = sbf + FQ + 2 * FKV;

    const int tid  = threadIdx.x;
    const int lane = tid & 31;
    const int w    = tid >> 5;          // 0..7
    const int lr   = lane >> 2;
    const int lc   = (lane & 3) << 1;
    const int q0   = (gridDim.x - 1 - blockIdx.x) << 7;   // heavy tiles first
    const int head = blockIdx.y;
    const int b    = blockIdx.z;
    const size_t base = ((size_t)b * SEQ) * LDQKV + head * DH;
    const float CE = 0.18033688011f;    // log2(e)/8
    const int wr = q0 + (w << 4);       // warp's first q row

    // load Q tile
#pragma unroll
    for (int i = 0; i < 4; i++) {
        const int idx = tid + (i << 8);
        const int r = idx >> 3, ch = idx & 7;
        cp16(qb + r * 144 + (ch << 4), qkv + base + (size_t)(q0 + r) * LDQKV + (ch << 3));
    }
    auto load_kv = [&](int kv0, int buf) {
#pragma unroll
        for (int i = 0; i < 2; i++) {
            const int idx = tid + (i << 8);
            const int r = idx >> 3, ch = idx & 7;
            const size_t g = base + (size_t)(kv0 + r) * LDQKV + (ch << 3);
            cp16(kb + buf * FKV + r * 144 + (ch << 4), qkv + 1024 + g);
            cp16(vb + buf * FKV + r * 144 + (ch << 4), qkv + 2048 + g);
        }
        asm volatile("cp.async.commit_group;" ::: "memory");
    };

    load_kv(0, 0);
    asm volatile("cp.async.wait_group 0;" ::: "memory");
    __syncthreads();

    float m[2] = {-1e30f, -1e30f}, l[2] = {0.f, 0.f};
    float o[8][4];
#pragma unroll
    for (int j = 0; j < 8; j++)
#pragma unroll
        for (int e = 0; e < 4; e++) o[j][e] = 0.f;

    const int iters = (q0 >> 6) + 2;
    for (int it = 0; it < iters; it++) {
        const int buf = it & 1;
        const int kv0 = it << 6;
        if (it + 1 < iters) load_kv((it + 1) << 6, buf ^ 1);

        if (kv0 <= wr + 15) {
            float sacc[8][4];
#pragma unroll
            for (int j = 0; j < 8; j++)
#pragma unroll
                for (int e = 0; e < 4; e++) sacc[j][e] = 0.f;
#pragma unroll
            for (int kk = 0; kk < 4; kk++) {
                uint32_t af[4];
                {
                    const int row  = (w << 4) + (lane & 7) + (((lane >> 3) & 1) << 3);
                    const int colh = (kk << 4) + ((lane >> 4) << 3);
                    ldsm4(af, qb + row * 144 + (colh << 1));
                }
#pragma unroll
                for (int p = 0; p < 4; p++) {
                    uint32_t bf[4];
                    const int row  = (p << 4) + (lane & 7) + ((lane >= 16) << 3);
                    const int colh = (kk << 4) + (((lane >> 3) & 1) << 3);
                    ldsm4(bf, kb + buf * FKV + row * 144 + (colh << 1));
                    mma16816(sacc[2 * p],     af, &bf[0]);
                    mma16816(sacc[2 * p + 1], af, &bf[2]);
                }
            }

            if (kv0 + 63 > wr) {
#pragma unroll
                for (int j = 0; j < 8; j++)
#pragma unroll
                    for (int e = 0; e < 4; e++) {
                        const int row = wr + lr + ((e >> 1) << 3);
                        const int col = kv0 + (j << 3) + lc + (e & 1);
                        if (col > row) sacc[j][e] = -1e30f;
                    }
            }

#pragma unroll
            for (int h = 0; h < 2; h++) {
                float mx = -1e30f;
#pragma unroll
                for (int j = 0; j < 8; j++)
                    mx = fmaxf(mx, fmaxf(sacc[j][2 * h], sacc[j][2 * h + 1]));
                mx = fmaxf(mx, __shfl_xor_sync(0xffffffffu, mx, 1));
                mx = fmaxf(mx, __shfl_xor_sync(0xffffffffu, mx, 2));
                const float mn = fmaxf(m[h], mx);
                const float alpha = ex2((m[h] - mn) * CE);
                m[h] = mn;
                float rsum = 0.f;
#pragma unroll
                for (int j = 0; j < 8; j++) {
                    sacc[j][2 * h]     = ex2((sacc[j][2 * h]     - mn) * CE);
                    sacc[j][2 * h + 1] = ex2((sacc[j][2 * h + 1] - mn) * CE);
                    rsum += sacc[j][2 * h] + sacc[j][2 * h + 1];
                }
                rsum += __shfl_xor_sync(0xffffffffu, rsum, 1);
                rsum += __shfl_xor_sync(0xffffffffu, rsum, 2);
                l[h] = l[h] * alpha + rsum;
#pragma unroll
                for (int j = 0; j < 8; j++) {
                    o[j][2 * h]     *= alpha;
                    o[j][2 * h + 1] *= alpha;
                }
            }

#pragma unroll
            for (int kk = 0; kk < 4; kk++) {
                uint32_t pa[4];
                {
                    __half2 t0 = __floats2half2_rn(sacc[2 * kk][0],     sacc[2 * kk][1]);
                    __half2 t1 = __floats2half2_rn(sacc[2 * kk][2],     sacc[2 * kk][3]);
                    __half2 t2 = __floats2half2_rn(sacc[2 * kk + 1][0], sacc[2 * kk + 1][1]);
                    __half2 t3 = __floats2half2_rn(sacc[2 * kk + 1][2], sacc[2 * kk + 1][3]);
                    pa[0] = *(uint32_t*)&t0; pa[1] = *(uint32_t*)&t1;
                    pa[2] = *(uint32_t*)&t2; pa[3] = *(uint32_t*)&t3;
                }
#pragma unroll
                for (int d = 0; d < 4; d++) {
                    uint32_t vf[4];
                    const int row  = (kk << 4) + (lane & 15);
                    const int colh = (d << 4) + ((lane >> 4) << 3);
                    ldsm4t(vf, vb + buf * FKV + row * 144 + (colh << 1));
                    mma16816(o[2 * d],     pa, &vf[0]);
                    mma16816(o[2 * d + 1], pa, &vf[2]);
                }
            }
        }

        asm volatile("cp.async.wait_group 0;" ::: "memory");
        __syncthreads();
    }

    const float inv0 = 1.f / l[0], inv1 = 1.f / l[1];
    const size_t obase = ((size_t)b * SEQ) * DM + head * DH;
#pragma unroll
    for (int j = 0; j < 8; j++) {
        const int col = (j << 3) + lc;
        const int r0 = wr + lr;
        *(__half2*)&at[obase + (size_t)r0 * DM + col] =
            __floats2half2_rn(o[j][0] * inv0, o[j][1] * inv0);
        *(__half2*)&at[obase + (size_t)(r0 + 8) * DM + col] =
            __floats2half2_rn(o[j][2] * inv1, o[j][3] * inv1);
    }
}

// ============================================================
// launch
// ============================================================
extern "C" void kernel_launch(void* const* d_in, const int* in_sizes, int n_in,
                              void* d_out, int out_size) {
    const float* x    = (const float*)d_in[0];
    const float* wq   = (const float*)d_in[1];
    const float* wk   = (const float*)d_in[2];
    const float* wv   = (const float*)d_in[3];
    const float* wo   = (const float*)d_in[4];
    const float* bo   = (const float*)d_in[5];
    const float* w1   = (const float*)d_in[6];
    const float* b1   = (const float*)d_in[7];
    const float* w2   = (const float*)d_in[8];
    const float* b2   = (const float*)d_in[9];
    const float* ln1s = (const float*)d_in[10];
    const float* ln1b = (const float*)d_in[11];
    const float* ln2s = (const float*)d_in[12];
    const float* ln2b = (const float*)d_in[13];
    float* out = (float*)d_out;

    __half *h, *qkv, *at, *h2, *ff;
    float* x1;
    __half *wqkvt, *wot, *w1t, *w2t;
    cudaGetSymbolAddress((void**)&h,     g_h);
    cudaGetSymbolAddress((void**)&qkv,   g_qkv);
    cudaGetSymbolAddress((void**)&at,    g_at);
    cudaGetSymbolAddress((void**)&x1,    g_x1);
    cudaGetSymbolAddress((void**)&h2,    g_h2);
    cudaGetSymbolAddress((void**)&ff,    g_ff);
    cudaGetSymbolAddress((void**)&wqkvt, g_wqkv);
    cudaGetSymbolAddress((void**)&wot,   g_wo);
    cudaGetSymbolAddress((void**)&w1t,   g_w1);
    cudaGetSymbolAddress((void**)&w2t,   g_w2);

    const int SMEM = 2 * STAGEB;   // 73728 bytes -> 2 CTAs/SM
    cudaFuncSetAttribute(hgemm_kernel, cudaFuncAttributeMaxDynamicSharedMemorySize, SMEM);
    cudaFuncSetAttribute(flash_kernel, cudaFuncAttributeMaxDynamicSharedMemorySize, FSMEM);

    // all weight transposes in one launch
    wtrans_all<<<12288, 256>>>(wq, wk, wv, wo, w1, w2, wqkvt, wot, w1t, w2t);

    // LN1 -> h (fp16)
    ln_kernel<<<BT, 256>>>(x, ln1s, ln1b, h);

    const dim3 gQKV(3 * DM / 128, BT / 128);
    const dim3 gD(DM / 128, BT / 128);
    const dim3 gF(DFFN / 128, BT / 128);
    const dim3 gAt(SEQ / 128, NH, 2);

    // fused QKV projection (fp16 out)
    hgemm_kernel<<<gQKV, 256, SMEM>>>(h, wqkvt, nullptr, nullptr,
                                      nullptr, qkv, 3 * DM, DM, 0);
    // tensor-core flash attention (fp16 out)
    flash_kernel<<<gAt, 256, FSMEM>>>(qkv, at);
    // out-proj + bias + residual -> x1 (fp32)
    hgemm_kernel<<<gD, 256, SMEM>>>(at, wot, bo, x, x1, nullptr, DM, DM, 1 | 2);
    // LN2 -> h2 (fp16)
    ln_kernel<<<BT, 256>>>(x1, ln2s, ln2b, h2);
    // FFN1 + bias + GELU -> ff (fp16)
    hgemm_kernel<<<gF, 256, SMEM>>>(h2, w1t, b1, nullptr, nullptr, ff, DFFN, DM, 1 | 4);
    // FFN2 + bias + residual -> out (fp32)
    hgemm_kernel<<<gD, 256, SMEM>>>(ff, w2t, b2, x1, out, nullptr, DM, DFFN, 1 | 2);
}